// round 3
// baseline (speedup 1.0000x reference)
#include <cuda_runtime.h>
#include <math.h>

#define Bn 64
#define Cn 3
#define Hn 512
#define Wn 512
#define HW (Hn * Wn)
#define CUT_H 256
#define CUT_W 256

struct __align__(16) BatchParams {
    float m00, m01, m10, m11;
    float tx, ty;
    float bb, cc, ss;
    int   flip, cut, y0, x0;
    int   vec;   // 1 = rotated (vector gather path)
    int   wsh;   // log2 warp-tile width (5,4,3,2); height = 32 >> wsh
    int   pad0, pad1;
};

__device__ BatchParams g_params[Bn];

__global__ void precompute_params_kernel(
    const float* __restrict__ u_angle, const float* __restrict__ u_scale,
    const float* __restrict__ u_trans, const float* __restrict__ u_bright,
    const float* __restrict__ u_contrast, const float* __restrict__ u_sat,
    const int* __restrict__ m_flip, const int* __restrict__ m_rot,
    const int* __restrict__ m_scale, const int* __restrict__ m_trans,
    const int* __restrict__ m_bright, const int* __restrict__ m_contrast,
    const int* __restrict__ m_sat, const int* __restrict__ m_cut,
    const int* __restrict__ y0, const int* __restrict__ x0)
{
    int b = threadIdx.x;
    if (b >= Bn) return;
    const float PI = 3.14159265358979323846f;
    float angle = (m_rot[b] > 0) ? (u_angle[b] * 2.0f - 1.0f) * PI : 0.0f;
    float sc    = (m_scale[b] > 0) ? (u_scale[b] * 2.0f - 1.0f) * 0.2f + 1.0f : 1.0f;
    float tr    = (m_trans[b] > 0) ? (u_trans[b] * 2.0f - 1.0f) * 0.125f : 0.0f;
    float ca = cosf(angle);
    float sa = sinf(angle);
    BatchParams p;
    p.m00 = sc * ca;  p.m01 = -sc * sa;
    p.m10 = sc * sa;  p.m11 =  sc * ca;
    p.tx = tr; p.ty = tr;
    p.bb = (m_bright[b]   > 0) ? u_bright[b] * 0.2f   : 0.0f;
    p.cc = (m_contrast[b] > 0) ? u_contrast[b] + 0.5f : 1.0f;
    p.ss = (m_sat[b]      > 0) ? u_sat[b] * 2.0f      : 1.0f;
    p.flip = m_flip[b];
    p.cut  = m_cut[b];
    p.y0 = y0[b];
    p.x0 = x0[b];

    // Gather-footprint cost model: pick warp-tile shape minimizing
    // (#load instr) * (lines per instr) + store lines.
    float am00 = fabsf(p.m00), am01 = fabsf(p.m01);
    float am10 = fabsf(p.m10), am11 = fabsf(p.m11);
    p.vec = (m_rot[b] > 0) ? 1 : 0;
    p.wsh = 5;
    if (p.vec) {
        float best = 1e30f;
        int best_wsh = 3;
        #pragma unroll
        for (int wsh = 2; wsh <= 5; wsh++) {
            float w = (float)(1 << wsh);
            float h = 32.0f / w;
            float rows = w * am10 + h * am11 + 1.0f;
            float xl   = 1.0f + (w * am00 + h * am01 + 4.0f) * (1.0f / 32.0f);
            float cost = 7.0f * rows * xl + 3.0f * h;
            if (cost < best) { best = cost; best_wsh = wsh; }
        }
        p.wsh = best_wsh;
    }
    g_params[b] = p;
}

__device__ __forceinline__ float reflect_coord(float v, float size) {
    v = fabsf(v + 0.5f);
    v = fmodf(v, 2.0f * size);
    v = fminf(v, 2.0f * size - v);
    return fminf(fmaxf(v - 0.5f, 0.0f), size - 1.0f);
}

__device__ __forceinline__ float clip1(float v) {
    return fminf(fmaxf(v, -1.0f), 1.0f);
}

__device__ __forceinline__ void color_and_store(
    float r0, float r1, float r2, const BatchParams& p,
    float* __restrict__ out, size_t out_idx)
{
    r0 = clip1(clip1(r0 + p.bb) * p.cc);
    r1 = clip1(clip1(r1 + p.bb) * p.cc);
    r2 = clip1(clip1(r2 + p.bb) * p.cc);
    const float gray = (r0 + r1 + r2) * (1.0f / 3.0f);
    r0 = clip1(gray + p.ss * (r0 - gray));
    r1 = clip1(gray + p.ss * (r1 - gray));
    r2 = clip1(gray + p.ss * (r2 - gray));
    out[out_idx]          = r0;
    out[out_idx + HW]     = r1;
    out[out_idx + 2 * HW] = r2;
}

__global__ void __launch_bounds__(256) augment_kernel(
    const float* __restrict__ images,
    const float* __restrict__ noise,
    float* __restrict__ out)
{
    const int b = blockIdx.y;
    const BatchParams p = g_params[b];

    // Per-batch adaptive warp-tile mapping: warp tile (w = 1<<wsh, h = 32>>wsh),
    // block = 2x4 warps, covering a (2w x 4h) pixel tile. Pure permutation of
    // threads -> pixels, so output-identical for any wsh.
    const int wsh  = p.wsh;
    const int hsh  = 5 - wsh;
    const int lane = threadIdx.x & 31;
    const int warp = threadIdx.x >> 5;
    const int bwsh = 8 - wsh;                 // log2(blocks across x)
    const int bx = blockIdx.x & ((1 << bwsh) - 1);
    const int by = blockIdx.x >> bwsh;
    const int x = (bx << (wsh + 1)) | ((warp & 1) << wsh) | (lane & ((1 << wsh) - 1));
    const int y = (by << (hsh + 2)) | ((warp >> 1) << hsh) | (lane >> wsh);

    const size_t img_base = (size_t)b * (Cn * HW);
    const size_t out_idx  = img_base + (size_t)y * Wn + x;

    const bool incut = (p.cut > 0) &&
                       (y >= p.y0) && (y < p.y0 + CUT_H) &&
                       (x >= p.x0) && (x < p.x0 + CUT_W);
    if (incut) {
        out[out_idx]          = noise[out_idx];
        out[out_idx + HW]     = noise[out_idx + HW];
        out[out_idx + 2 * HW] = noise[out_idx + 2 * HW];
        return;
    }

    const float gx0 = fmaf((float)x, 2.0f / (Wn - 1), -1.0f);
    const float gy0 = fmaf((float)y, 2.0f / (Hn - 1), -1.0f);
    const float gx = p.m00 * gx0 + p.m01 * gy0 + p.tx;
    const float gy = p.m10 * gx0 + p.m11 * gy0 + p.ty;

    float fx = ((gx + 1.0f) * (float)Wn - 1.0f) * 0.5f;
    float fy = ((gy + 1.0f) * (float)Hn - 1.0f) * 0.5f;
    fx = reflect_coord(fx, (float)Wn);
    fy = reflect_coord(fy, (float)Hn);

    const float x0f = floorf(fx);
    const float y0f = floorf(fy);
    const float wx = fx - x0f;
    const float wy = fy - y0f;

    int xi0 = (int)x0f;
    int xi1 = min(xi0 + 1, Wn - 1);
    const int yi0 = (int)y0f;
    const int yi1 = min(yi0 + 1, Hn - 1);

    if (p.flip > 0) {
        xi0 = (Wn - 1) - xi0;
        xi1 = (Wn - 1) - xi1;
    }

    if (p.vec) {
        // ---- rotated: vectorized x-pair gather ----
        // Taps live at {xlo, xhi} with xhi-xlo <= 1. Load the aligned float4
        // containing xlo; only when xlo&3==3 and xhi==xlo+1 is one predicated
        // scalar extra needed. Flip & border-clamp fold into the shared lerp
        // weight wp (value = a + wp*(b-a), a at xlo, b at xlo+1).
        const int xlo = min(xi0, xi1);
        const int xhi = max(xi0, xi1);
        const int xa  = xlo & ~3;
        const int j0  = xlo - xa;             // 0..3
        const bool need_e = (xhi - xa) == 4;

        float wp = (p.flip > 0) ? (1.0f - wx) : wx;
        if (xlo == xhi) wp = 0.0f;

        const float* row00 = images + img_base + (size_t)yi0 * Wn + xa;
        const float* row10 = images + img_base + (size_t)yi1 * Wn + xa;

        float4 q00 = *(const float4*)(row00);
        float4 q10 = *(const float4*)(row10);
        float4 q01 = *(const float4*)(row00 + HW);
        float4 q11 = *(const float4*)(row10 + HW);
        float4 q02 = *(const float4*)(row00 + 2 * HW);
        float4 q12 = *(const float4*)(row10 + 2 * HW);
        float e00 = 0.f, e10 = 0.f, e01 = 0.f, e11 = 0.f, e02 = 0.f, e12 = 0.f;
        if (need_e) {
            e00 = __ldg(row00 + 4);          e10 = __ldg(row10 + 4);
            e01 = __ldg(row00 + HW + 4);     e11 = __ldg(row10 + HW + 4);
            e02 = __ldg(row00 + 2*HW + 4);   e12 = __ldg(row10 + 2*HW + 4);
        }

        const bool s1 = (j0 & 1) != 0;
        const bool s2 = (j0 & 2) != 0;
        float r[3];
        {
            // channel 0
            float a, bq;
            a  = s2 ? (s1 ? q00.w : q00.z) : (s1 ? q00.y : q00.x);
            bq = s2 ? (s1 ? e00   : q00.w) : (s1 ? q00.z : q00.y);
            const float top = a + wp * (bq - a);
            a  = s2 ? (s1 ? q10.w : q10.z) : (s1 ? q10.y : q10.x);
            bq = s2 ? (s1 ? e10   : q10.w) : (s1 ? q10.z : q10.y);
            const float bot = a + wp * (bq - a);
            r[0] = top + wy * (bot - top);
        }
        {
            float a, bq;
            a  = s2 ? (s1 ? q01.w : q01.z) : (s1 ? q01.y : q01.x);
            bq = s2 ? (s1 ? e01   : q01.w) : (s1 ? q01.z : q01.y);
            const float top = a + wp * (bq - a);
            a  = s2 ? (s1 ? q11.w : q11.z) : (s1 ? q11.y : q11.x);
            bq = s2 ? (s1 ? e11   : q11.w) : (s1 ? q11.z : q11.y);
            const float bot = a + wp * (bq - a);
            r[1] = top + wy * (bot - top);
        }
        {
            float a, bq;
            a  = s2 ? (s1 ? q02.w : q02.z) : (s1 ? q02.y : q02.x);
            bq = s2 ? (s1 ? e02   : q02.w) : (s1 ? q02.z : q02.y);
            const float top = a + wp * (bq - a);
            a  = s2 ? (s1 ? q12.w : q12.z) : (s1 ? q12.y : q12.x);
            bq = s2 ? (s1 ? e12   : q12.w) : (s1 ? q12.z : q12.y);
            const float bot = a + wp * (bq - a);
            r[2] = top + wy * (bot - top);
        }
        color_and_store(r[0], r[1], r[2], p, out, out_idx);
    } else {
        // ---- unrotated: scalar gather (already ~2 lines/instr) ----
        const int o00 = yi0 * Wn + xi0;
        const int o01 = yi0 * Wn + xi1;
        const int o10 = yi1 * Wn + xi0;
        const int o11 = yi1 * Wn + xi1;

        float v00[Cn], v01[Cn], v10[Cn], v11[Cn];
        #pragma unroll
        for (int c = 0; c < Cn; c++) {
            const float* ic = images + img_base + (size_t)c * HW;
            v00[c] = __ldg(ic + o00);
            v01[c] = __ldg(ic + o01);
            v10[c] = __ldg(ic + o10);
            v11[c] = __ldg(ic + o11);
        }
        float r[Cn];
        #pragma unroll
        for (int c = 0; c < Cn; c++) {
            const float top = v00[c] + wx * (v01[c] - v00[c]);
            const float bot = v10[c] + wx * (v11[c] - v10[c]);
            r[c] = top + wy * (bot - top);
        }
        color_and_store(r[0], r[1], r[2], p, out, out_idx);
    }
}

extern "C" void kernel_launch(void* const* d_in, const int* in_sizes, int n_in,
                              void* d_out, int out_size) {
    const float* images     = (const float*)d_in[0];
    const float* u_angle    = (const float*)d_in[1];
    const float* u_scale    = (const float*)d_in[2];
    const float* u_trans    = (const float*)d_in[3];
    const float* u_bright   = (const float*)d_in[4];
    const float* u_contrast = (const float*)d_in[5];
    const float* u_sat      = (const float*)d_in[6];
    const float* noise      = (const float*)d_in[7];
    const int*   m_flip     = (const int*)d_in[8];
    const int*   m_rot      = (const int*)d_in[9];
    const int*   m_scale    = (const int*)d_in[10];
    const int*   m_trans    = (const int*)d_in[11];
    const int*   m_bright   = (const int*)d_in[12];
    const int*   m_contrast = (const int*)d_in[13];
    const int*   m_sat      = (const int*)d_in[14];
    const int*   m_cut      = (const int*)d_in[15];
    const int*   y0         = (const int*)d_in[16];
    const int*   x0         = (const int*)d_in[17];
    float* out = (float*)d_out;

    precompute_params_kernel<<<1, 64>>>(
        u_angle, u_scale, u_trans, u_bright, u_contrast, u_sat,
        m_flip, m_rot, m_scale, m_trans, m_bright, m_contrast,
        m_sat, m_cut, y0, x0);

    dim3 block(256);
    dim3 grid(1024, Bn);
    augment_kernel<<<grid, block>>>(images, noise, out);
}